// round 2
// baseline (speedup 1.0000x reference)
#include <cuda_runtime.h>

// Focal cross-entropy, N rows x 2 classes, scalar-sum output.
// inputs: d_in[0] = pred [N,2] f32, d_in[1] = gold [N] f32. out: 1 f32.
//
// 2-class identity: with d = p1 - p0, t = exp(-|d|), L = log(1+t):
//   log_softmax = { d>=0: lp1=-L, lp0=-(d+L) ; d<0: lp0=-L, lp1=-(|d|+L) }
//   prb(hi) = 1/(1+t), prb(lo) = t/(1+t)
//   focal0 = prb1^2, focal1 = prb0^2   (since 1-prb_c = prb_other)
// loss = oh0*(-lp0)*prb1^2 + oh1*(-lp1)*prb0^2
//   oh1 = (g>=0.5)?0.25:0 ; oh0 = (1-oh1)*0.75

__device__ double g_acc;

__global__ void fl_zero_kernel() { g_acc = 0.0; }

__device__ __forceinline__ float row_loss(float p0, float p1, float g) {
    float d   = p1 - p0;
    float ad  = fabsf(d);
    float t   = __expf(-ad);                 // MUFU.EX2 (+mul)
    float s   = 1.0f + t;
    float L   = __logf(s);                   // MUFU.LG2 (+mul)
    float inv = __fdividef(1.0f, s);         // MUFU.RCP
    float pr_hi = inv;                       // prob of larger-logit class
    float pr_lo = t * inv;

    bool pos = (d >= 0.0f);                  // p1 is the larger logit
    float nlp0 = pos ? (ad + L) : L;         // -log_softmax[0]
    float nlp1 = pos ? L : (ad + L);         // -log_softmax[1]
    float pr0  = pos ? pr_lo : pr_hi;
    float pr1  = pos ? pr_hi : pr_lo;

    float oh1 = (g >= 0.5f) ? 0.25f : 0.0f;
    float oh0 = (1.0f - oh1) * 0.75f;

    return oh0 * nlp0 * (pr1 * pr1) + oh1 * nlp1 * (pr0 * pr0);
}

__global__ void __launch_bounds__(256)
fl_main_kernel(const float4* __restrict__ pred4,  // [N/2] float4 (2 rows each)
               const float4* __restrict__ gold4,  // [N/4] float4
               long long n4)                      // N/4
{
    long long i = (long long)blockIdx.x * blockDim.x + threadIdx.x;
    float acc = 0.0f;
    if (i < n4) {
        float4 g  = gold4[i];
        float4 pa = pred4[2 * i];       // rows 4i, 4i+1
        float4 pb = pred4[2 * i + 1];   // rows 4i+2, 4i+3
        acc  = row_loss(pa.x, pa.y, g.x);
        acc += row_loss(pa.z, pa.w, g.y);
        acc += row_loss(pb.x, pb.y, g.z);
        acc += row_loss(pb.z, pb.w, g.w);
    }

    // warp reduce
    #pragma unroll
    for (int off = 16; off > 0; off >>= 1)
        acc += __shfl_down_sync(0xFFFFFFFFu, acc, off);

    __shared__ float warp_sums[8];
    int lane = threadIdx.x & 31;
    int wid  = threadIdx.x >> 5;
    if (lane == 0) warp_sums[wid] = acc;
    __syncthreads();

    if (wid == 0) {
        float v = (lane < 8) ? warp_sums[lane] : 0.0f;
        #pragma unroll
        for (int off = 4; off > 0; off >>= 1)
            v += __shfl_down_sync(0xFFFFFFFFu, v, off);
        if (lane == 0)
            atomicAdd(&g_acc, (double)v);
    }
}

__global__ void fl_tail_kernel(const float* __restrict__ pred,
                               const float* __restrict__ gold,
                               long long start, long long n)
{
    // handles n % 4 leftover rows (none for N=16777216, kept for safety)
    if (threadIdx.x == 0 && blockIdx.x == 0) {
        float acc = 0.0f;
        for (long long r = start; r < n; r++)
            acc += row_loss(pred[2 * r], pred[2 * r + 1], gold[r]);
        if (acc != 0.0f) atomicAdd(&g_acc, (double)acc);
    }
}

__global__ void fl_finalize_kernel(float* __restrict__ out) {
    out[0] = (float)g_acc;  // CORR = 1.0
}

extern "C" void kernel_launch(void* const* d_in, const int* in_sizes, int n_in,
                              void* d_out, int out_size)
{
    const float* pred = (const float*)d_in[0];
    const float* gold = (const float*)d_in[1];
    float* out = (float*)d_out;

    long long n  = in_sizes[1];      // rows (gold element count)
    long long n4 = n >> 2;

    fl_zero_kernel<<<1, 1>>>();

    int threads = 256;
    long long blocks = (n4 + threads - 1) / threads;
    if (blocks > 0)
        fl_main_kernel<<<(unsigned)blocks, threads>>>(
            (const float4*)pred, (const float4*)gold, n4);

    if (n & 3)
        fl_tail_kernel<<<1, 32>>>(pred, gold, n4 * 4, n);

    fl_finalize_kernel<<<1, 1>>>(out);
}